// round 8
// baseline (speedup 1.0000x reference)
#include <cuda_runtime.h>
#include <math.h>
#include <stdint.h>

// ---------------------------------------------------------------------------
// GRUEncoder: B=256, T=512, IN_DIM=75, H=256, 2-layer GRU + FC
//   K0: xg0 = x @ W_ih0^T + b_ih0
//   K1: layer0 recurrence (4-CTA clusters, k-packed f32x2, mbarrier exchange)
//   K2: xg1 = out0 @ W_ih1^T + b_ih1
//   K3: layer1 recurrence -> hT
//   K4: emb = hT @ fc_W^T + fc_b
// Recurrence: single 8-row group per cluster, W_hh read once per step from
// SMEM as pre-paired u64 (k-packed), h broadcast as u64 pairs -> no dup MOVs.
// ---------------------------------------------------------------------------

#define B_  256
#define T_  512
#define H_  256
#define G3_ 768
#define INDIM_ 75

__device__ float g_xg[(size_t)B_ * T_ * G3_];
__device__ float g_out0[(size_t)B_ * T_ * H_];
__device__ float g_hT[(size_t)B_ * H_];

typedef unsigned long long u64;

__device__ __forceinline__ u64 pack2(float lo, float hi) {
    u64 d; asm("mov.b64 %0, {%1, %2};" : "=l"(d) : "f"(lo), "f"(hi)); return d;
}
__device__ __forceinline__ void unpack2(u64 v, float& lo, float& hi) {
    asm("mov.b64 {%0, %1}, %2;" : "=f"(lo), "=f"(hi) : "l"(v));
}
__device__ __forceinline__ u64 ffma2(u64 a, u64 b, u64 c) {
    u64 d; asm("fma.rn.f32x2 %0, %1, %2, %3;" : "=l"(d) : "l"(a), "l"(b), "l"(c)); return d;
}
__device__ __forceinline__ uint32_t smem_u32(const void* p) {
    uint32_t a;
    asm("{ .reg .u64 t; cvta.to.shared.u64 t, %1; cvt.u32.u64 %0, t; }" : "=r"(a) : "l"(p));
    return a;
}
__device__ __forceinline__ uint32_t mapa_(uint32_t addr, uint32_t rank) {
    uint32_t r; asm("mapa.shared::cluster.u32 %0, %1, %2;" : "=r"(r) : "r"(addr), "r"(rank));
    return r;
}
__device__ __forceinline__ uint32_t ctarank_() {
    uint32_t r; asm("mov.u32 %0, %%cluster_ctarank;" : "=r"(r)); return r;
}
#define CLUSTER_BAR() do { \
    asm volatile("barrier.cluster.arrive.aligned;" ::: "memory"); \
    asm volatile("barrier.cluster.wait.aligned;"   ::: "memory"); } while (0)

__device__ __forceinline__ void mbar_init(uint32_t addr, uint32_t cnt) {
    asm volatile("mbarrier.init.shared.b64 [%0], %1;" :: "r"(addr), "r"(cnt) : "memory");
}
__device__ __forceinline__ void mbar_expect_tx(uint32_t addr, uint32_t bytes) {
    asm volatile("mbarrier.arrive.expect_tx.shared.b64 _, [%0], %1;"
                 :: "r"(addr), "r"(bytes) : "memory");
}
__device__ __forceinline__ void st_async_u32(uint32_t raddr, uint32_t v, uint32_t rmbar) {
    asm volatile("st.async.shared::cluster.mbarrier::complete_tx::bytes.b32 [%0], %1, [%2];"
                 :: "r"(raddr), "r"(v), "r"(rmbar) : "memory");
}
__device__ __forceinline__ void mbar_wait_parity(uint32_t addr, uint32_t parity) {
    uint32_t done;
    asm volatile(
        "{\n\t.reg .pred p;\n\t"
        "mbarrier.try_wait.parity.acquire.cluster.shared::cta.b64 p, [%1], %2;\n\t"
        "selp.b32 %0, 1, 0, p;\n\t}"
        : "=r"(done) : "r"(addr), "r"(parity) : "memory");
    if (!done) {
        asm volatile(
            "{\n\t.reg .pred P1;\n\t"
            "WL_%=:\n\t"
            "mbarrier.try_wait.parity.acquire.cluster.shared::cta.b64 P1, [%0], %1, 0x989680;\n\t"
            "@P1 bra.uni WD_%=;\n\t"
            "bra.uni WL_%=;\n\t"
            "WD_%=:\n\t}"
            :: "r"(addr), "r"(parity) : "memory");
    }
}

__device__ __forceinline__ float sigm(float x)  { return __fdividef(1.f, 1.f + __expf(-x)); }
__device__ __forceinline__ float tanhf_(float x){ return __fdividef(2.f, 1.f + __expf(-2.f * x)) - 1.f; }

// ---------------------------------------------------------------------------
// Tiled GEMM: C[M,N] = A[M,K] @ B[N,K]^T + bias[N]   (unchanged, known-good)
// ---------------------------------------------------------------------------
__global__ __launch_bounds__(256)
void gemm_bias_kernel(const float* __restrict__ A, const float* __restrict__ Bm,
                      const float* __restrict__ bias, float* __restrict__ C,
                      int M, int N, int K)
{
    __shared__ __align__(16) float As[8][132];
    __shared__ __align__(16) float Bs[8][68];

    const int tx = threadIdx.x & 15;
    const int ty = threadIdx.x >> 4;
    const int m0 = blockIdx.y * 128;
    const int n0 = blockIdx.x * 64;

    u64 acc[4][4];
#pragma unroll
    for (int p = 0; p < 4; p++)
#pragma unroll
        for (int c = 0; c < 4; c++) acc[p][c] = 0ull;

    for (int k0 = 0; k0 < K; k0 += 8) {
#pragma unroll
        for (int i = 0; i < 4; i++) {
            int idx = threadIdx.x + i * 256;
            int m = idx >> 3, k = idx & 7;
            float v = 0.0f;
            if (k0 + k < K) v = A[(size_t)(m0 + m) * K + (k0 + k)];
            As[k][m] = v;
        }
#pragma unroll
        for (int i = 0; i < 2; i++) {
            int idx = threadIdx.x + i * 256;
            int n = idx >> 3, k = idx & 7;
            float v = 0.0f;
            if (k0 + k < K) v = Bm[(size_t)(n0 + n) * K + (k0 + k)];
            Bs[k][n] = v;
        }
        __syncthreads();

#pragma unroll
        for (int k = 0; k < 8; k++) {
            float4 a0 = *(const float4*)&As[k][ty * 8];
            float4 a1 = *(const float4*)&As[k][ty * 8 + 4];
            float4 b  = *(const float4*)&Bs[k][tx * 4];
            u64 ap[4] = { pack2(a0.x, a0.y), pack2(a0.z, a0.w),
                          pack2(a1.x, a1.y), pack2(a1.z, a1.w) };
            u64 bb[4] = { pack2(b.x, b.x), pack2(b.y, b.y),
                          pack2(b.z, b.z), pack2(b.w, b.w) };
#pragma unroll
            for (int p = 0; p < 4; p++)
#pragma unroll
                for (int c = 0; c < 4; c++)
                    acc[p][c] = ffma2(ap[p], bb[c], acc[p][c]);
        }
        __syncthreads();
    }

    float bv[4];
#pragma unroll
    for (int c = 0; c < 4; c++) bv[c] = bias[n0 + tx * 4 + c];

#pragma unroll
    for (int p = 0; p < 4; p++) {
        float lo[4], hi[4];
#pragma unroll
        for (int c = 0; c < 4; c++) unpack2(acc[p][c], lo[c], hi[c]);
        int r0 = m0 + ty * 8 + 2 * p;
        float4 o0 = make_float4(lo[0] + bv[0], lo[1] + bv[1], lo[2] + bv[2], lo[3] + bv[3]);
        float4 o1 = make_float4(hi[0] + bv[0], hi[1] + bv[1], hi[2] + bv[2], hi[3] + bv[3]);
        *(float4*)&C[(size_t)r0 * N + n0 + tx * 4]       = o0;
        *(float4*)&C[(size_t)(r0 + 1) * N + n0 + tx * 4] = o1;
    }
}

// ---------------------------------------------------------------------------
// Cluster GRU recurrence, k-packed f32x2.
// Cluster of 4 CTAs, 8 batch rows per cluster, 32 clusters = 128 CTAs.
// CTA rank c owns units [c*64, c*64+64): 192 gate rows of W_hh in SMEM,
// stored as u64 pairs Ws2[kp][g*64+u] = (W[..][2kp], W[..][2kp+1]).
// 256 threads = 64 units x 4 k-slices (32 kp each). Thread (u, s):
//   GEMM: acc[gate][row] over its kp range; f32x2 lanes = (even-k, odd-k).
//   Scalarize lo+hi; cross-slice reduce via smem (f32); finalize rows 2s,2s+1;
//   st.async h (b32) to all 4 CTAs' next-phase h buffer; mbarrier tx = 8192B.
// h buffer: hb[2][128 kp][8 rows] u64 = (h_{2kp}, h_{2kp+1}) per row.
// SMEM: Ws2 192KB | hb 16KB | red 18KB | mbar = 231488 B.
// ---------------------------------------------------------------------------
#define WS_BYTES  196608
#define HB_OFF    WS_BYTES
#define RED_OFF   (HB_OFF + 16384)
#define MB_OFF    (RED_OFF + 18432)
#define GRU_SMEM  (MB_OFF + 64)           // 231488

template<bool WRITE_OUT, bool WRITE_HT>
__global__ void __cluster_dims__(4, 1, 1) __launch_bounds__(256, 1)
gru_cluster_kernel(const float* __restrict__ xg, const float* __restrict__ Whh,
                   const float* __restrict__ bhh,
                   float* __restrict__ out, float* __restrict__ hT)
{
    extern __shared__ __align__(16) char smem[];
    u64*   Ws2 = (u64*)smem;                  // [128 kp][192 (g*64+u)]
    u64*   hb  = (u64*)(smem + HB_OFF);       // [2][128 kp][8 rows]
    float* red = (float*)(smem + RED_OFF);    // [((s*3+g)*3+j)*2+b][64 u]
    u64*   mbs = (u64*)(smem + MB_OFF);

    const int tid = threadIdx.x;
    const int u   = tid & 63;
    const int s   = tid >> 6;                 // k-slice / row-pair owner
    const uint32_t crank = ctarank_();
    const int cu  = (int)crank * 64 + u;
    const int row0 = (blockIdx.x >> 2) * 8;

    // ---- stage W_hh as k-paired u64, k-major ----
    for (int idx = tid; idx < 192 * 64; idx += 256) {
        int o = idx % 192, q = idx / 192;     // q = k/4
        int g = o >> 6, uo = o & 63;
        int grow = g * 256 + (int)crank * 64 + uo;
        float4 w = ((const float4*)Whh)[grow * 64 + q];
        Ws2[(size_t)(2 * q)     * 192 + o] = pack2(w.x, w.y);
        Ws2[(size_t)(2 * q + 1) * 192 + o] = pack2(w.z, w.w);
    }
    for (int i = tid; i < 2048; i += 256) hb[i] = 0ull;
    if (tid == 0) mbar_init(smem_u32(&mbs[0]), 1);
    __syncthreads();
    CLUSTER_BAR();   // weights, h zeros, mbarrier visible cluster-wide

    const float br = bhh[cu], bz = bhh[256 + cu], bn = bhh[512 + cu];

    uint32_t mlocal = smem_u32(&mbs[0]);
    // h slot (parity 0) for unit cu, row 2s: u64 index (cu>>1)*8 + 2s, half cu&1
    uint32_t slot0 = smem_u32(&hb[(size_t)(cu >> 1) * 8 + 2 * s]) + (uint32_t)(cu & 1) * 4u;
    uint32_t haddr[4], maddr[4];
#pragma unroll
    for (int i = 0; i < 4; i++) {
        uint32_t rk = (crank + i) & 3;
        haddr[i] = mapa_(slot0, rk);
        maddr[i] = mapa_(mlocal, rk);
    }

    const int r0g = row0 + 2 * s;
    const float* px0 = xg + ((size_t)r0g * T_) * G3_ + cu;
    const float* px1 = px0 + (size_t)T_ * G3_;
    float* po0 = WRITE_OUT ? out + ((size_t)r0g * T_) * H_ + cu : nullptr;
    float* po1 = WRITE_OUT ? po0 + (size_t)T_ * H_ : nullptr;

    float hp0 = 0.f, hp1 = 0.f;

    for (int t = 0; t < T_; t++) {
        // xg prefetch (independent of h(t))
        float x_r0 = px0[0], x_z0 = px0[256], x_n0 = px0[512];
        float x_r1 = px1[0], x_z1 = px1[256], x_n1 = px1[512];

        if (t > 0) mbar_wait_parity(mlocal, (uint32_t)((t - 1) & 1));

        // GEMM: kp in [32s, 32s+32), 8 rows, 3 gates; lanes = (even-k, odd-k)
        u64 acc[3][8];
#pragma unroll
        for (int g = 0; g < 3; g++)
#pragma unroll
            for (int r = 0; r < 8; r++) acc[g][r] = 0ull;
        {
            const u64* wsp = Ws2 + (size_t)(s * 32) * 192;
            const u64* hk  = hb + (size_t)(t & 1) * 1024 + (size_t)(s * 32) * 8;
#pragma unroll 2
            for (int kp = 0; kp < 32; kp++) {
                u64 wr = wsp[u], wz = wsp[64 + u], wn = wsp[128 + u];
                ulonglong2 h01 = *(const ulonglong2*)(hk);
                ulonglong2 h23 = *(const ulonglong2*)(hk + 2);
                ulonglong2 h45 = *(const ulonglong2*)(hk + 4);
                ulonglong2 h67 = *(const ulonglong2*)(hk + 6);
                acc[0][0] = ffma2(h01.x, wr, acc[0][0]);
                acc[0][1] = ffma2(h01.y, wr, acc[0][1]);
                acc[0][2] = ffma2(h23.x, wr, acc[0][2]);
                acc[0][3] = ffma2(h23.y, wr, acc[0][3]);
                acc[0][4] = ffma2(h45.x, wr, acc[0][4]);
                acc[0][5] = ffma2(h45.y, wr, acc[0][5]);
                acc[0][6] = ffma2(h67.x, wr, acc[0][6]);
                acc[0][7] = ffma2(h67.y, wr, acc[0][7]);
                acc[1][0] = ffma2(h01.x, wz, acc[1][0]);
                acc[1][1] = ffma2(h01.y, wz, acc[1][1]);
                acc[1][2] = ffma2(h23.x, wz, acc[1][2]);
                acc[1][3] = ffma2(h23.y, wz, acc[1][3]);
                acc[1][4] = ffma2(h45.x, wz, acc[1][4]);
                acc[1][5] = ffma2(h45.y, wz, acc[1][5]);
                acc[1][6] = ffma2(h67.x, wz, acc[1][6]);
                acc[1][7] = ffma2(h67.y, wz, acc[1][7]);
                acc[2][0] = ffma2(h01.x, wn, acc[2][0]);
                acc[2][1] = ffma2(h01.y, wn, acc[2][1]);
                acc[2][2] = ffma2(h23.x, wn, acc[2][2]);
                acc[2][3] = ffma2(h23.y, wn, acc[2][3]);
                acc[2][4] = ffma2(h45.x, wn, acc[2][4]);
                acc[2][5] = ffma2(h45.y, wn, acc[2][5]);
                acc[2][6] = ffma2(h67.x, wn, acc[2][6]);
                acc[2][7] = ffma2(h67.y, wn, acc[2][7]);
                wsp += 192; hk += 8;
            }
        }

        // scalarize (even+odd k halves)
        float pg[3][8];
#pragma unroll
        for (int g = 0; g < 3; g++)
#pragma unroll
            for (int r = 0; r < 8; r++) {
                float lo, hi; unpack2(acc[g][r], lo, hi); pg[g][r] = lo + hi;
            }

        // write partials for the 3 row-pairs other slices finalize
#pragma unroll
        for (int p = 0; p < 4; p++) {
            if (p != s) {
                int j = p - (p > s ? 1 : 0);
#pragma unroll
                for (int g = 0; g < 3; g++) {
                    red[((((size_t)s * 3 + g) * 3 + j) * 2 + 0) * 64 + u] = pg[g][2 * p];
                    red[((((size_t)s * 3 + g) * 3 + j) * 2 + 1) * 64 + u] = pg[g][2 * p + 1];
                }
            }
        }
        __syncthreads();

        // arm next-phase completion (precedes this CTA's stores)
        if (tid == 0 && t < T_ - 1) mbar_expect_tx(mlocal, 8192);

        // gather own row-pair s across the 4 slices
        float pre0[3], pre1[3];
#pragma unroll
        for (int g = 0; g < 3; g++) { pre0[g] = pg[g][2 * s]; pre1[g] = pg[g][2 * s + 1]; }
#pragma unroll
        for (int sp = 0; sp < 4; sp++) {
            if (sp != s) {
                int j = s - (s > sp ? 1 : 0);
#pragma unroll
                for (int g = 0; g < 3; g++) {
                    pre0[g] += red[((((size_t)sp * 3 + g) * 3 + j) * 2 + 0) * 64 + u];
                    pre1[g] += red[((((size_t)sp * 3 + g) * 3 + j) * 2 + 1) * 64 + u];
                }
            }
        }

        float r0 = sigm(x_r0 + pre0[0] + br);
        float z0 = sigm(x_z0 + pre0[1] + bz);
        float n0 = tanhf_(x_n0 + r0 * (pre0[2] + bn));
        float h0 = n0 + z0 * (hp0 - n0);

        float r1 = sigm(x_r1 + pre1[0] + br);
        float z1 = sigm(x_z1 + pre1[1] + bz);
        float n1 = tanhf_(x_n1 + r1 * (pre1[2] + bn));
        float h1 = n1 + z1 * (hp1 - n1);

        if (WRITE_OUT) { po0[0] = h0; po1[0] = h1; po0 += H_; po1 += H_; }

        if (t < T_ - 1) {
            uint32_t poff = (uint32_t)((t + 1) & 1) * 8192u;
            uint32_t b0 = __float_as_uint(h0), b1 = __float_as_uint(h1);
#pragma unroll
            for (int i = 0; i < 4; i++) {
                st_async_u32(haddr[i] + poff,     b0, maddr[i]);
                st_async_u32(haddr[i] + poff + 8, b1, maddr[i]);   // row 2s+1
            }
        }

        hp0 = h0; hp1 = h1;
        px0 += G3_; px1 += G3_;
    }

    if (WRITE_HT) {
        hT[(size_t)r0g * H_ + cu]       = hp0;
        hT[(size_t)(r0g + 1) * H_ + cu] = hp1;
    }
    CLUSTER_BAR();   // no CTA exits with peers' remote accesses in flight
}

// ---------------------------------------------------------------------------
extern "C" void kernel_launch(void* const* d_in, const int* in_sizes, int n_in,
                              void* d_out, int out_size)
{
    const float* x     = (const float*)d_in[0];
    const float* W_ih0 = (const float*)d_in[1];
    const float* W_hh0 = (const float*)d_in[2];
    const float* b_ih0 = (const float*)d_in[3];
    const float* b_hh0 = (const float*)d_in[4];
    const float* W_ih1 = (const float*)d_in[5];
    const float* W_hh1 = (const float*)d_in[6];
    const float* b_ih1 = (const float*)d_in[7];
    const float* b_hh1 = (const float*)d_in[8];
    const float* fc_W  = (const float*)d_in[9];
    const float* fc_b  = (const float*)d_in[10];
    float* out = (float*)d_out;

    float *xg, *out0, *hT;
    cudaGetSymbolAddress((void**)&xg,   g_xg);
    cudaGetSymbolAddress((void**)&out0, g_out0);
    cudaGetSymbolAddress((void**)&hT,   g_hT);

    static int smem_set = 0;
    if (!smem_set) {
        cudaFuncSetAttribute(gru_cluster_kernel<true,  false>,
                             cudaFuncAttributeMaxDynamicSharedMemorySize, GRU_SMEM);
        cudaFuncSetAttribute(gru_cluster_kernel<false, true>,
                             cudaFuncAttributeMaxDynamicSharedMemorySize, GRU_SMEM);
        smem_set = 1;
    }

    const int MT = B_ * T_;

    gemm_bias_kernel<<<dim3(G3_ / 64, MT / 128), 256>>>(x, W_ih0, b_ih0, xg, MT, G3_, INDIM_);
    gru_cluster_kernel<true,  false><<<128, 256, GRU_SMEM>>>(xg, W_hh0, b_hh0, out0, nullptr);
    gemm_bias_kernel<<<dim3(G3_ / 64, MT / 128), 256>>>(out0, W_ih1, b_ih1, xg, MT, G3_, H_);
    gru_cluster_kernel<false, true><<<128, 256, GRU_SMEM>>>(xg, W_hh1, b_hh1, nullptr, hT);
    gemm_bias_kernel<<<dim3(H_ / 64, B_ / 128), 256>>>(hT, fc_W, fc_b, out, B_, H_, H_);
}

// round 12
// speedup vs baseline: 1.0756x; 1.0756x over previous
#include <cuda_runtime.h>
#include <math.h>
#include <stdint.h>

// ---------------------------------------------------------------------------
// GRUEncoder: B=256, T=512, IN_DIM=75, H=256, 2-layer GRU + FC
//   K0: xg0 = x @ W_ih0^T + b_ih0
//   K1: layer0 recurrence (4-CTA clusters, k-packed f32x2, per-source mbars)
//   K2: xg1 = out0 @ W_ih1^T + b_ih1
//   K3: layer1 recurrence -> hT
//   K4: emb = hT @ fc_W^T + fc_b
// Recurrence: 8 rows/cluster, W_hh in SMEM as k-paired u64 (read once/step),
// h exchange via st.async to 4 per-source mbarriers; each k-slice waits only
// on ITS producer CTA's barrier -> warps start next step as data lands.
// ---------------------------------------------------------------------------

#define B_  256
#define T_  512
#define H_  256
#define G3_ 768
#define INDIM_ 75

__device__ float g_xg[(size_t)B_ * T_ * G3_];
__device__ float g_out0[(size_t)B_ * T_ * H_];
__device__ float g_hT[(size_t)B_ * H_];

typedef unsigned long long u64;

__device__ __forceinline__ u64 pack2(float lo, float hi) {
    u64 d; asm("mov.b64 %0, {%1, %2};" : "=l"(d) : "f"(lo), "f"(hi)); return d;
}
__device__ __forceinline__ void unpack2(u64 v, float& lo, float& hi) {
    asm("mov.b64 {%0, %1}, %2;" : "=f"(lo), "=f"(hi) : "l"(v));
}
__device__ __forceinline__ u64 ffma2(u64 a, u64 b, u64 c) {
    u64 d; asm("fma.rn.f32x2 %0, %1, %2, %3;" : "=l"(d) : "l"(a), "l"(b), "l"(c)); return d;
}
__device__ __forceinline__ uint32_t smem_u32(const void* p) {
    uint32_t a;
    asm("{ .reg .u64 t; cvta.to.shared.u64 t, %1; cvt.u32.u64 %0, t; }" : "=r"(a) : "l"(p));
    return a;
}
__device__ __forceinline__ uint32_t mapa_(uint32_t addr, uint32_t rank) {
    uint32_t r; asm("mapa.shared::cluster.u32 %0, %1, %2;" : "=r"(r) : "r"(addr), "r"(rank));
    return r;
}
__device__ __forceinline__ uint32_t ctarank_() {
    uint32_t r; asm("mov.u32 %0, %%cluster_ctarank;" : "=r"(r)); return r;
}
#define CLUSTER_BAR() do { \
    asm volatile("barrier.cluster.arrive.aligned;" ::: "memory"); \
    asm volatile("barrier.cluster.wait.aligned;"   ::: "memory"); } while (0)

__device__ __forceinline__ void mbar_init(uint32_t addr, uint32_t cnt) {
    asm volatile("mbarrier.init.shared.b64 [%0], %1;" :: "r"(addr), "r"(cnt) : "memory");
}
__device__ __forceinline__ void mbar_expect_tx(uint32_t addr, uint32_t bytes) {
    asm volatile("mbarrier.arrive.expect_tx.shared.b64 _, [%0], %1;"
                 :: "r"(addr), "r"(bytes) : "memory");
}
__device__ __forceinline__ void st_async_u32(uint32_t raddr, uint32_t v, uint32_t rmbar) {
    asm volatile("st.async.shared::cluster.mbarrier::complete_tx::bytes.b32 [%0], %1, [%2];"
                 :: "r"(raddr), "r"(v), "r"(rmbar) : "memory");
}
__device__ __forceinline__ void mbar_wait_parity(uint32_t addr, uint32_t parity) {
    uint32_t done;
    asm volatile(
        "{\n\t.reg .pred p;\n\t"
        "mbarrier.try_wait.parity.acquire.cluster.shared::cta.b64 p, [%1], %2;\n\t"
        "selp.b32 %0, 1, 0, p;\n\t}"
        : "=r"(done) : "r"(addr), "r"(parity) : "memory");
    if (!done) {
        asm volatile(
            "{\n\t.reg .pred P1;\n\t"
            "WL_%=:\n\t"
            "mbarrier.try_wait.parity.acquire.cluster.shared::cta.b64 P1, [%0], %1, 0x989680;\n\t"
            "@P1 bra.uni WD_%=;\n\t"
            "bra.uni WL_%=;\n\t"
            "WD_%=:\n\t}"
            :: "r"(addr), "r"(parity) : "memory");
    }
}

__device__ __forceinline__ float sigm(float x)  { return __fdividef(1.f, 1.f + __expf(-x)); }
__device__ __forceinline__ float tanhf_(float x){ return __fdividef(2.f, 1.f + __expf(-2.f * x)) - 1.f; }

// ---------------------------------------------------------------------------
// Tiled GEMM: C[M,N] = A[M,K] @ B[N,K]^T + bias[N]   (unchanged, known-good)
// ---------------------------------------------------------------------------
__global__ __launch_bounds__(256)
void gemm_bias_kernel(const float* __restrict__ A, const float* __restrict__ Bm,
                      const float* __restrict__ bias, float* __restrict__ C,
                      int M, int N, int K)
{
    __shared__ __align__(16) float As[8][132];
    __shared__ __align__(16) float Bs[8][68];

    const int tx = threadIdx.x & 15;
    const int ty = threadIdx.x >> 4;
    const int m0 = blockIdx.y * 128;
    const int n0 = blockIdx.x * 64;

    u64 acc[4][4];
#pragma unroll
    for (int p = 0; p < 4; p++)
#pragma unroll
        for (int c = 0; c < 4; c++) acc[p][c] = 0ull;

    for (int k0 = 0; k0 < K; k0 += 8) {
#pragma unroll
        for (int i = 0; i < 4; i++) {
            int idx = threadIdx.x + i * 256;
            int m = idx >> 3, k = idx & 7;
            float v = 0.0f;
            if (k0 + k < K) v = A[(size_t)(m0 + m) * K + (k0 + k)];
            As[k][m] = v;
        }
#pragma unroll
        for (int i = 0; i < 2; i++) {
            int idx = threadIdx.x + i * 256;
            int n = idx >> 3, k = idx & 7;
            float v = 0.0f;
            if (k0 + k < K) v = Bm[(size_t)(n0 + n) * K + (k0 + k)];
            Bs[k][n] = v;
        }
        __syncthreads();

#pragma unroll
        for (int k = 0; k < 8; k++) {
            float4 a0 = *(const float4*)&As[k][ty * 8];
            float4 a1 = *(const float4*)&As[k][ty * 8 + 4];
            float4 b  = *(const float4*)&Bs[k][tx * 4];
            u64 ap[4] = { pack2(a0.x, a0.y), pack2(a0.z, a0.w),
                          pack2(a1.x, a1.y), pack2(a1.z, a1.w) };
            u64 bb[4] = { pack2(b.x, b.x), pack2(b.y, b.y),
                          pack2(b.z, b.z), pack2(b.w, b.w) };
#pragma unroll
            for (int p = 0; p < 4; p++)
#pragma unroll
                for (int c = 0; c < 4; c++)
                    acc[p][c] = ffma2(ap[p], bb[c], acc[p][c]);
        }
        __syncthreads();
    }

    float bv[4];
#pragma unroll
    for (int c = 0; c < 4; c++) bv[c] = bias[n0 + tx * 4 + c];

#pragma unroll
    for (int p = 0; p < 4; p++) {
        float lo[4], hi[4];
#pragma unroll
        for (int c = 0; c < 4; c++) unpack2(acc[p][c], lo[c], hi[c]);
        int r0 = m0 + ty * 8 + 2 * p;
        float4 o0 = make_float4(lo[0] + bv[0], lo[1] + bv[1], lo[2] + bv[2], lo[3] + bv[3]);
        float4 o1 = make_float4(hi[0] + bv[0], hi[1] + bv[1], hi[2] + bv[2], hi[3] + bv[3]);
        *(float4*)&C[(size_t)r0 * N + n0 + tx * 4]       = o0;
        *(float4*)&C[(size_t)(r0 + 1) * N + n0 + tx * 4] = o1;
    }
}

// ---------------------------------------------------------------------------
// Cluster GRU recurrence, k-packed f32x2, per-source mbarriers.
// Cluster of 4 CTAs, 8 batch rows, 32 clusters = 128 CTAs.
// CTA rank c owns units [c*64, c*64+64): 192 gate rows of W_hh in SMEM as
// u64 k-pairs Ws2[kp][g*64+u]. 256 threads = 64 units x 4 k-slices (32 kp).
// Slice s consumes h of units [64s,64s+64) == produced by CTA rank s, so
// slice s waits ONLY on mbar[s] (tx = 2048B from CTA s's 256 threads x 2 x 4B).
// All h exchanged via st.async (incl. self, local DSMEM ~38cyc); each slice's
// u==0 thread re-arms mbar[s] at loop top (margin: one full GEMM).
// SMEM: Ws2 192KB | hb [2][128 kp][8 rows] u64 16KB | red f32 18KB | mbs[4].
// ---------------------------------------------------------------------------
#define WS_BYTES  196608
#define HB_OFF    WS_BYTES
#define RED_OFF   (HB_OFF + 16384)
#define MB_OFF    (RED_OFF + 18432)
#define GRU_SMEM  (MB_OFF + 64)           // 231488

template<bool WRITE_OUT, bool WRITE_HT>
__global__ void __cluster_dims__(4, 1, 1) __launch_bounds__(256, 1)
gru_cluster_kernel(const float* __restrict__ xg, const float* __restrict__ Whh,
                   const float* __restrict__ bhh,
                   float* __restrict__ out, float* __restrict__ hT)
{
    extern __shared__ __align__(16) char smem[];
    u64*   Ws2 = (u64*)smem;                  // [128 kp][192 (g*64+u)]
    u64*   hb  = (u64*)(smem + HB_OFF);       // [2][128 kp][8 rows]
    float* red = (float*)(smem + RED_OFF);    // [((s*3+g)*3+j)*2+b][64 u]
    u64*   mbs = (u64*)(smem + MB_OFF);       // [4] per-source mbarriers

    const int tid = threadIdx.x;
    const int u   = tid & 63;
    const int s   = tid >> 6;                 // k-slice == producer CTA rank
    const uint32_t crank = ctarank_();
    const int cu  = (int)crank * 64 + u;
    const int row0 = (blockIdx.x >> 2) * 8;

    // ---- stage W_hh as k-paired u64, k-major ----
    for (int idx = tid; idx < 192 * 64; idx += 256) {
        int o = idx % 192, q = idx / 192;     // q = k/4
        int g = o >> 6, uo = o & 63;
        int grow = g * 256 + (int)crank * 64 + uo;
        float4 w = ((const float4*)Whh)[grow * 64 + q];
        Ws2[(size_t)(2 * q)     * 192 + o] = pack2(w.x, w.y);
        Ws2[(size_t)(2 * q + 1) * 192 + o] = pack2(w.z, w.w);
    }
    for (int i = tid; i < 2048; i += 256) hb[i] = 0ull;
    if (tid < 4) mbar_init(smem_u32(&mbs[tid]), 1);
    __syncthreads();
    CLUSTER_BAR();   // weights, h zeros, mbarriers visible cluster-wide

    const float br = bhh[cu], bz = bhh[256 + cu], bn = bhh[512 + cu];

    // wait target: my own barrier for my slice's producer CTA
    const uint32_t mwait = smem_u32(&mbs[s]);
    // send targets: h slot for (unit cu, rows 2s/2s+1) + my-rank barrier, in
    // every cluster CTA
    uint32_t slot0 = smem_u32(&hb[(size_t)(cu >> 1) * 8 + 2 * s]) + (uint32_t)(cu & 1) * 4u;
    uint32_t mown  = smem_u32(&mbs[crank]);
    uint32_t haddr[4], maddr[4];
#pragma unroll
    for (int i = 0; i < 4; i++) {
        uint32_t rk = (crank + i) & 3;
        haddr[i] = mapa_(slot0, rk);
        maddr[i] = mapa_(mown,  rk);
    }

    const int r0g = row0 + 2 * s;
    const float* px0 = xg + ((size_t)r0g * T_) * G3_ + cu;
    const float* px1 = px0 + (size_t)T_ * G3_;
    float* po0 = WRITE_OUT ? out + ((size_t)r0g * T_) * H_ + cu : nullptr;
    float* po1 = WRITE_OUT ? po0 + (size_t)T_ * H_ : nullptr;

    float hp0 = 0.f, hp1 = 0.f;

    for (int t = 0; t < T_; t++) {
        // xg prefetch (independent of h(t)) — in flight during the wait
        float x_r0 = px0[0], x_z0 = px0[256], x_n0 = px0[512];
        float x_r1 = px1[0], x_z1 = px1[256], x_n1 = px1[512];

        // wait only for MY slice's producer data; re-arm for next phase.
        if (t > 0) mbar_wait_parity(mwait, (uint32_t)((t - 1) & 1));
        if (u == 0 && t < T_ - 1) mbar_expect_tx(mwait, 2048);

        // GEMM: kp in [32s, 32s+32), 8 rows, 3 gates; lanes = (even-k, odd-k)
        u64 acc[3][8];
#pragma unroll
        for (int g = 0; g < 3; g++)
#pragma unroll
            for (int r = 0; r < 8; r++) acc[g][r] = 0ull;
        {
            const u64* wsp = Ws2 + (size_t)(s * 32) * 192;
            const u64* hk  = hb + (size_t)(t & 1) * 1024 + (size_t)(s * 32) * 8;
#pragma unroll 2
            for (int kp = 0; kp < 32; kp++) {
                u64 wr = wsp[u], wz = wsp[64 + u], wn = wsp[128 + u];
                ulonglong2 h01 = *(const ulonglong2*)(hk);
                ulonglong2 h23 = *(const ulonglong2*)(hk + 2);
                ulonglong2 h45 = *(const ulonglong2*)(hk + 4);
                ulonglong2 h67 = *(const ulonglong2*)(hk + 6);
                acc[0][0] = ffma2(h01.x, wr, acc[0][0]);
                acc[0][1] = ffma2(h01.y, wr, acc[0][1]);
                acc[0][2] = ffma2(h23.x, wr, acc[0][2]);
                acc[0][3] = ffma2(h23.y, wr, acc[0][3]);
                acc[0][4] = ffma2(h45.x, wr, acc[0][4]);
                acc[0][5] = ffma2(h45.y, wr, acc[0][5]);
                acc[0][6] = ffma2(h67.x, wr, acc[0][6]);
                acc[0][7] = ffma2(h67.y, wr, acc[0][7]);
                acc[1][0] = ffma2(h01.x, wz, acc[1][0]);
                acc[1][1] = ffma2(h01.y, wz, acc[1][1]);
                acc[1][2] = ffma2(h23.x, wz, acc[1][2]);
                acc[1][3] = ffma2(h23.y, wz, acc[1][3]);
                acc[1][4] = ffma2(h45.x, wz, acc[1][4]);
                acc[1][5] = ffma2(h45.y, wz, acc[1][5]);
                acc[1][6] = ffma2(h67.x, wz, acc[1][6]);
                acc[1][7] = ffma2(h67.y, wz, acc[1][7]);
                acc[2][0] = ffma2(h01.x, wn, acc[2][0]);
                acc[2][1] = ffma2(h01.y, wn, acc[2][1]);
                acc[2][2] = ffma2(h23.x, wn, acc[2][2]);
                acc[2][3] = ffma2(h23.y, wn, acc[2][3]);
                acc[2][4] = ffma2(h45.x, wn, acc[2][4]);
                acc[2][5] = ffma2(h45.y, wn, acc[2][5]);
                acc[2][6] = ffma2(h67.x, wn, acc[2][6]);
                acc[2][7] = ffma2(h67.y, wn, acc[2][7]);
                wsp += 192; hk += 8;
            }
        }

        // scalarize (even+odd k halves)
        float pg[3][8];
#pragma unroll
        for (int g = 0; g < 3; g++)
#pragma unroll
            for (int r = 0; r < 8; r++) {
                float lo, hi; unpack2(acc[g][r], lo, hi); pg[g][r] = lo + hi;
            }

        // write partials for the 3 row-pairs other slices finalize
#pragma unroll
        for (int p = 0; p < 4; p++) {
            if (p != s) {
                int j = p - (p > s ? 1 : 0);
#pragma unroll
                for (int g = 0; g < 3; g++) {
                    red[((((size_t)s * 3 + g) * 3 + j) * 2 + 0) * 64 + u] = pg[g][2 * p];
                    red[((((size_t)s * 3 + g) * 3 + j) * 2 + 1) * 64 + u] = pg[g][2 * p + 1];
                }
            }
        }
        __syncthreads();

        // gather own row-pair s across the 4 slices
        float pre0[3], pre1[3];
#pragma unroll
        for (int g = 0; g < 3; g++) { pre0[g] = pg[g][2 * s]; pre1[g] = pg[g][2 * s + 1]; }
#pragma unroll
        for (int sp = 0; sp < 4; sp++) {
            if (sp != s) {
                int j = s - (s > sp ? 1 : 0);
#pragma unroll
                for (int g = 0; g < 3; g++) {
                    pre0[g] += red[((((size_t)sp * 3 + g) * 3 + j) * 2 + 0) * 64 + u];
                    pre1[g] += red[((((size_t)sp * 3 + g) * 3 + j) * 2 + 1) * 64 + u];
                }
            }
        }

        float r0 = sigm(x_r0 + pre0[0] + br);
        float z0 = sigm(x_z0 + pre0[1] + bz);
        float n0 = tanhf_(x_n0 + r0 * (pre0[2] + bn));
        float h0 = n0 + z0 * (hp0 - n0);

        float r1 = sigm(x_r1 + pre1[0] + br);
        float z1 = sigm(x_z1 + pre1[1] + bz);
        float n1 = tanhf_(x_n1 + r1 * (pre1[2] + bn));
        float h1 = n1 + z1 * (hp1 - n1);

        if (WRITE_OUT) { po0[0] = h0; po1[0] = h1; po0 += H_; po1 += H_; }

        if (t < T_ - 1) {
            uint32_t poff = (uint32_t)((t + 1) & 1) * 8192u;
            uint32_t b0 = __float_as_uint(h0), b1 = __float_as_uint(h1);
#pragma unroll
            for (int i = 0; i < 4; i++) {
                st_async_u32(haddr[i] + poff,     b0, maddr[i]);
                st_async_u32(haddr[i] + poff + 8, b1, maddr[i]);   // row 2s+1
            }
        }

        hp0 = h0; hp1 = h1;
        px0 += G3_; px1 += G3_;
    }

    if (WRITE_HT) {
        hT[(size_t)r0g * H_ + cu]       = hp0;
        hT[(size_t)(r0g + 1) * H_ + cu] = hp1;
    }
    CLUSTER_BAR();   // no CTA exits with peers' remote accesses in flight
}

// ---------------------------------------------------------------------------
extern "C" void kernel_launch(void* const* d_in, const int* in_sizes, int n_in,
                              void* d_out, int out_size)
{
    const float* x     = (const float*)d_in[0];
    const float* W_ih0 = (const float*)d_in[1];
    const float* W_hh0 = (const float*)d_in[2];
    const float* b_ih0 = (const float*)d_in[3];
    const float* b_hh0 = (const float*)d_in[4];
    const float* W_ih1 = (const float*)d_in[5];
    const float* W_hh1 = (const float*)d_in[6];
    const float* b_ih1 = (const float*)d_in[7];
    const float* b_hh1 = (const float*)d_in[8];
    const float* fc_W  = (const float*)d_in[9];
    const float* fc_b  = (const float*)d_in[10];
    float* out = (float*)d_out;

    float *xg, *out0, *hT;
    cudaGetSymbolAddress((void**)&xg,   g_xg);
    cudaGetSymbolAddress((void**)&out0, g_out0);
    cudaGetSymbolAddress((void**)&hT,   g_hT);

    static int smem_set = 0;
    if (!smem_set) {
        cudaFuncSetAttribute(gru_cluster_kernel<true,  false>,
                             cudaFuncAttributeMaxDynamicSharedMemorySize, GRU_SMEM);
        cudaFuncSetAttribute(gru_cluster_kernel<false, true>,
                             cudaFuncAttributeMaxDynamicSharedMemorySize, GRU_SMEM);
        smem_set = 1;
    }

    const int MT = B_ * T_;

    gemm_bias_kernel<<<dim3(G3_ / 64, MT / 128), 256>>>(x, W_ih0, b_ih0, xg, MT, G3_, INDIM_);
    gru_cluster_kernel<true,  false><<<128, 256, GRU_SMEM>>>(xg, W_hh0, b_hh0, out0, nullptr);
    gemm_bias_kernel<<<dim3(G3_ / 64, MT / 128), 256>>>(out0, W_ih1, b_ih1, xg, MT, G3_, H_);
    gru_cluster_kernel<false, true><<<128, 256, GRU_SMEM>>>(xg, W_hh1, b_hh1, nullptr, hT);
    gemm_bias_kernel<<<dim3(H_ / 64, B_ / 128), 256>>>(hT, fc_W, fc_b, out, B_, H_, H_);
}